// round 1
// baseline (speedup 1.0000x reference)
#include <cuda_runtime.h>
#include <math.h>

#define NN 50000
#define EE 800000
#define BB 512
#define DD 128

// ---------------- scratch (static device globals; no allocation) ----------------
__device__ float g_agg[NN * DD];     // mean-aggregated features (scaled)
__device__ float g_h1[NN * DD];      // ping
__device__ float g_h2[NN * DD];      // pong
__device__ float g_pool[BB * DD];    // global max pool result
__device__ float g_invdeg[NN];
__device__ int   g_deg[NN];          // degree, then reused as fill cursor
__device__ int   g_rowptr[NN + 1];
__device__ int   g_col[EE];          // CSR column (src) indices grouped by dst
__device__ int   g_root[BB];

__device__ __forceinline__ float* buf_sel(int i) {
    return i == 1 ? g_h1 : (i == 2 ? g_h2 : g_agg);
}

// ---------------- CSR build ----------------
__global__ void k_zero_deg() {
    int i = blockIdx.x * blockDim.x + threadIdx.x;
    if (i < NN) g_deg[i] = 0;
}

__global__ void k_count(const int* __restrict__ dst) {
    int e = blockIdx.x * blockDim.x + threadIdx.x;
    if (e < EE) atomicAdd(&g_deg[dst[e]], 1);
}

// single-block exclusive scan over g_deg -> g_rowptr (N=50000, 49 tiles of 1024)
__global__ void k_scan() {
    __shared__ int sh[1024];
    __shared__ int carry;
    int tid = threadIdx.x;
    if (tid == 0) carry = 0;
    __syncthreads();
    for (int base = 0; base < NN; base += 1024) {
        int i = base + tid;
        int v = (i < NN) ? g_deg[i] : 0;
        sh[tid] = v;
        __syncthreads();
        for (int off = 1; off < 1024; off <<= 1) {
            int t = (tid >= off) ? sh[tid - off] : 0;
            __syncthreads();
            sh[tid] += t;
            __syncthreads();
        }
        int incl = sh[tid];
        if (i < NN) g_rowptr[i] = carry + (incl - v);
        __syncthreads();
        if (tid == 1023) carry += sh[1023];
        __syncthreads();
    }
    if (tid == 0) g_rowptr[NN] = carry;   // == EE
}

__global__ void k_invdeg_reset() {
    int i = blockIdx.x * blockDim.x + threadIdx.x;
    if (i < NN) {
        int d = g_deg[i];
        g_invdeg[i] = 1.0f / (float)(d > 1 ? d : 1);
        g_deg[i] = 0;   // reuse as cursor
    }
}

__global__ void k_fill(const int* __restrict__ src, const int* __restrict__ dst) {
    int e = blockIdx.x * blockDim.x + threadIdx.x;
    if (e < EE) {
        int d = dst[e];
        int pos = g_rowptr[d] + atomicAdd(&g_deg[d], 1);
        g_col[pos] = src[e];
    }
}

// ---------------- mean aggregation: warp per destination node ----------------
__global__ void k_agg(const float* __restrict__ ext_in, int in_sel) {
    int warp = (blockIdx.x * blockDim.x + threadIdx.x) >> 5;
    int lane = threadIdx.x & 31;
    if (warp >= NN) return;
    const float* hin = (in_sel < 0) ? ext_in : buf_sel(in_sel);
    int s = g_rowptr[warp];
    int e = g_rowptr[warp + 1];
    float4 acc = make_float4(0.f, 0.f, 0.f, 0.f);
    int i = s;
    for (; i + 2 <= e; i += 2) {
        int s0 = g_col[i];
        int s1 = g_col[i + 1];
        float4 v0 = *(const float4*)(hin + (size_t)s0 * DD + lane * 4);
        float4 v1 = *(const float4*)(hin + (size_t)s1 * DD + lane * 4);
        acc.x += v0.x + v1.x;
        acc.y += v0.y + v1.y;
        acc.z += v0.z + v1.z;
        acc.w += v0.w + v1.w;
    }
    if (i < e) {
        int s0 = g_col[i];
        float4 v0 = *(const float4*)(hin + (size_t)s0 * DD + lane * 4);
        acc.x += v0.x; acc.y += v0.y; acc.z += v0.z; acc.w += v0.w;
    }
    float iv = g_invdeg[warp];
    acc.x *= iv; acc.y *= iv; acc.z *= iv; acc.w *= iv;
    *(float4*)(g_agg + (size_t)warp * DD + lane * 4) = acc;
}

// ---------------- fused SAGE GEMM: out = relu([mean|x] @ [Wl;Wr] + bl) ----------------
// A: [N,256] (k<128 -> g_agg, k>=128 -> xin), B: [256,128], C: [N,128]
// tile 128x128x32, 256 threads, 8x8 micro-tile
#define AS_STRIDE 132
__global__ void __launch_bounds__(256) k_gemm(const float* __restrict__ ext_x, int x_sel,
                                              int out_sel,
                                              const float* __restrict__ Wl,
                                              const float* __restrict__ Wr,
                                              const float* __restrict__ bl) {
    const float* xin = (x_sel < 0) ? ext_x : buf_sel(x_sel);
    float* out = buf_sel(out_sel);

    __shared__ float As[32 * AS_STRIDE];   // [k][m], padded
    __shared__ float Bs[32 * 128];         // [k][j]

    int block_m = blockIdx.x * 128;
    int tid = threadIdx.x;
    int tx = tid & 15;         // 0..15 -> output cols tx*8..tx*8+7
    int ty = tid >> 4;         // 0..15 -> output rows ty*8..ty*8+7

    float acc[8][8];
#pragma unroll
    for (int i = 0; i < 8; i++)
#pragma unroll
        for (int j = 0; j < 8; j++) acc[i][j] = 0.f;

    for (int k0 = 0; k0 < 256; k0 += 32) {
        // A tile: 128 rows x 32 k
#pragma unroll
        for (int i = 0; i < 16; i++) {
            int e = tid + i * 256;     // 0..4095
            int m = e >> 5;
            int k = e & 31;
            int gm = block_m + m;
            int gk = k0 + k;
            float v = 0.f;
            if (gm < NN)
                v = (gk < 128) ? g_agg[(size_t)gm * DD + gk]
                               : xin[(size_t)gm * DD + (gk - 128)];
            As[k * AS_STRIDE + m] = v;
        }
        // B tile: 32 k x 128 j
#pragma unroll
        for (int i = 0; i < 16; i++) {
            int e = tid + i * 256;
            int k = e >> 7;
            int j = e & 127;
            int gk = k0 + k;
            Bs[k * 128 + j] = (gk < 128) ? Wl[gk * 128 + j] : Wr[(gk - 128) * 128 + j];
        }
        __syncthreads();
#pragma unroll
        for (int k = 0; k < 32; k++) {
            float a[8], b[8];
#pragma unroll
            for (int i = 0; i < 8; i++) a[i] = As[k * AS_STRIDE + ty * 8 + i];
#pragma unroll
            for (int j = 0; j < 8; j++) b[j] = Bs[k * 128 + tx * 8 + j];
#pragma unroll
            for (int i = 0; i < 8; i++)
#pragma unroll
                for (int j = 0; j < 8; j++) acc[i][j] += a[i] * b[j];
        }
        __syncthreads();
    }
#pragma unroll
    for (int i = 0; i < 8; i++) {
        int gm = block_m + ty * 8 + i;
        if (gm >= NN) continue;
#pragma unroll
        for (int j = 0; j < 8; j++) {
            int gj = tx * 8 + j;
            float v = acc[i][j] + bl[gj];
            out[(size_t)gm * DD + gj] = fmaxf(v, 0.f);
        }
    }
}

// ---------------- pooling + roots ----------------
__global__ void k_zero_pool() {
    int i = blockIdx.x * blockDim.x + threadIdx.x;
    if (i < BB * DD) ((int*)g_pool)[i] = 0;   // 0 bits == +0.0f, valid min for relu outputs
}

__global__ void k_pool(const int* __restrict__ batch) {
    int warp = (blockIdx.x * blockDim.x + threadIdx.x) >> 5;
    int lane = threadIdx.x & 31;
    if (warp >= NN) return;
    int b = batch[warp];
    float4 v = *(const float4*)(g_h1 + (size_t)warp * DD + lane * 4);
    int* p = (int*)g_pool + (size_t)b * DD + lane * 4;
    // values >= 0 (post-relu): int-bit compare is monotone
    atomicMax(p + 0, __float_as_int(v.x));
    atomicMax(p + 1, __float_as_int(v.y));
    atomicMax(p + 2, __float_as_int(v.z));
    atomicMax(p + 3, __float_as_int(v.w));
}

__global__ void k_roots(const int* __restrict__ batch) {
    int i = blockIdx.x * blockDim.x + threadIdx.x;
    if (i < NN) {
        int b = batch[i];
        if (i == 0 || batch[i - 1] != b) g_root[b] = i;
    }
}

// ---------------- per-graph MLP head ----------------
__global__ void __launch_bounds__(256) k_head(const float* __restrict__ x,
                                              const float* __restrict__ Wf1, const float* __restrict__ bf1,
                                              const float* __restrict__ Wf2, const float* __restrict__ bf2,
                                              const float* __restrict__ Wsm, const float* __restrict__ bsm,
                                              const float* __restrict__ Wnews, const float* __restrict__ bnews,
                                              const float* __restrict__ Wcat, const float* __restrict__ bcat,
                                              float* __restrict__ out) {
    int b = blockIdx.x;
    int t = threadIdx.x;
    __shared__ float p[128], xr[128], t1[256], t2[128], sres[4];
    if (t < 128) {
        p[t] = g_pool[(size_t)b * DD + t];
        xr[t] = x[(size_t)g_root[b] * DD + t];
    }
    __syncthreads();
    // t1 = relu(p @ Wf1 + bf1), 256 outputs
    {
        float acc = bf1[t];
#pragma unroll 4
        for (int k = 0; k < 128; k++) acc += p[k] * Wf1[k * 256 + t];
        t1[t] = fmaxf(acc, 0.f);
    }
    __syncthreads();
    if (t < 128) {
        float acc = bf2[t];
#pragma unroll 4
        for (int k = 0; k < 256; k++) acc += t1[k] * Wf2[k * 128 + t];
        t2[t] = fmaxf(acc, 0.f);
    }
    __syncthreads();
    if (t < 2) {
        float acc = bsm[t];
        for (int k = 0; k < 128; k++) acc += t2[k] * Wsm[k * 2 + t];
        sres[t] = fmaxf(acc, 0.f);
        float a2 = bnews[t];
        for (int k = 0; k < 128; k++) a2 += xr[k] * Wnews[k * 2 + t];
        sres[2 + t] = fmaxf(a2, 0.f);
    }
    __syncthreads();
    if (t == 0) {
        float o = bcat[0];
        for (int k = 0; k < 4; k++) o += sres[k] * Wcat[k];
        out[b] = 1.f / (1.f + expf(-o));
    }
}

// ---------------- launch ----------------
extern "C" void kernel_launch(void* const* d_in, const int* in_sizes, int n_in,
                              void* d_out, int out_size) {
    const float* x     = (const float*)d_in[0];
    const int*   ei    = (const int*)d_in[1];
    const int*   src   = ei;
    const int*   dst   = ei + EE;
    const int*   batch = (const int*)d_in[2];
    const float* Wl1 = (const float*)d_in[3];
    const float* Wr1 = (const float*)d_in[4];
    const float* bl1 = (const float*)d_in[5];
    const float* Wl2 = (const float*)d_in[6];
    const float* Wr2 = (const float*)d_in[7];
    const float* bl2 = (const float*)d_in[8];
    const float* Wl3 = (const float*)d_in[9];
    const float* Wr3 = (const float*)d_in[10];
    const float* bl3 = (const float*)d_in[11];
    const float* Wf1 = (const float*)d_in[12];
    const float* bf1 = (const float*)d_in[13];
    const float* Wf2 = (const float*)d_in[14];
    const float* bf2 = (const float*)d_in[15];
    const float* Wsm = (const float*)d_in[16];
    const float* bsm = (const float*)d_in[17];
    const float* Wnews = (const float*)d_in[18];
    const float* bnews = (const float*)d_in[19];
    const float* Wcat = (const float*)d_in[20];
    const float* bcat = (const float*)d_in[21];
    float* out = (float*)d_out;

    const int TB = 256;
    int gN = (NN + TB - 1) / TB;
    int gE = (EE + TB - 1) / TB;
    int gWarpN = (NN * 32 + TB - 1) / TB;   // warp-per-node grids
    int gGemm = (NN + 127) / 128;

    // CSR build
    k_zero_deg<<<gN, TB>>>();
    k_count<<<gE, TB>>>(dst);
    k_scan<<<1, 1024>>>();
    k_invdeg_reset<<<gN, TB>>>();
    k_fill<<<gE, TB>>>(src, dst);

    // layer 1: x -> h1
    k_agg<<<gWarpN, TB>>>(x, -1);
    k_gemm<<<gGemm, TB>>>(x, -1, 1, Wl1, Wr1, bl1);
    // layer 2: h1 -> h2
    k_agg<<<gWarpN, TB>>>(nullptr, 1);
    k_gemm<<<gGemm, TB>>>(nullptr, 1, 2, Wl2, Wr2, bl2);
    // layer 3: h2 -> h1
    k_agg<<<gWarpN, TB>>>(nullptr, 2);
    k_gemm<<<gGemm, TB>>>(nullptr, 2, 1, Wl3, Wr3, bl3);

    // pooling + roots + head
    k_zero_pool<<<(BB * DD + TB - 1) / TB, TB>>>();
    k_pool<<<gWarpN, TB>>>(batch);
    k_roots<<<gN, TB>>>(batch);
    k_head<<<BB, TB>>>(x, Wf1, bf1, Wf2, bf2, Wsm, bsm, Wnews, bnews, Wcat, bcat, out);
}

// round 3
// speedup vs baseline: 1.4206x; 1.4206x over previous
#include <cuda_runtime.h>
#include <cuda_bf16.h>
#include <math.h>
#include <stdint.h>

#define NN 50000
#define EE 800000
#define BB 512
#define DD 128
#define KK 256
#define TM 128
#define GEMM_BLOCKS ((NN + TM - 1) / TM)   // 391

// ---------------- scratch (static device globals; no allocation) ----------------
__device__ float g_agg[NN * DD];
__device__ float g_h1[NN * DD];
__device__ float g_h2[NN * DD];
__device__ __nv_bfloat16 g_Ahi[NN * KK];
__device__ __nv_bfloat16 g_Alo[NN * KK];
__device__ __nv_bfloat16 g_Whi[3][DD * KK];   // W^T: row n (out col), col k
__device__ __nv_bfloat16 g_Wlo[3][DD * KK];
__device__ float g_pool[BB * DD];
__device__ float g_invdeg[NN];
__device__ int   g_deg[NN];
__device__ int   g_rowptr[NN + 1];
__device__ int   g_col[EE];
__device__ int   g_root[BB];

__device__ __forceinline__ float* buf_sel(int i) {
    return i == 1 ? g_h1 : (i == 2 ? g_h2 : g_agg);
}

// ---------------- CSR build ----------------
__global__ void k_zero_deg() {
    int i = blockIdx.x * blockDim.x + threadIdx.x;
    if (i < NN) g_deg[i] = 0;
}
__global__ void k_count(const int* __restrict__ dst) {
    int e = blockIdx.x * blockDim.x + threadIdx.x;
    if (e < EE) atomicAdd(&g_deg[dst[e]], 1);
}
__global__ void k_scan() {
    __shared__ int sh[1024];
    __shared__ int carry;
    int tid = threadIdx.x;
    if (tid == 0) carry = 0;
    __syncthreads();
    for (int base = 0; base < NN; base += 1024) {
        int i = base + tid;
        int v = (i < NN) ? g_deg[i] : 0;
        sh[tid] = v;
        __syncthreads();
        for (int off = 1; off < 1024; off <<= 1) {
            int t = (tid >= off) ? sh[tid - off] : 0;
            __syncthreads();
            sh[tid] += t;
            __syncthreads();
        }
        int incl = sh[tid];
        if (i < NN) g_rowptr[i] = carry + (incl - v);
        __syncthreads();
        if (tid == 1023) carry += sh[1023];
        __syncthreads();
    }
    if (tid == 0) g_rowptr[NN] = carry;
}
__global__ void k_invdeg_reset() {
    int i = blockIdx.x * blockDim.x + threadIdx.x;
    if (i < NN) {
        int d = g_deg[i];
        g_invdeg[i] = 1.0f / (float)(d > 1 ? d : 1);
        g_deg[i] = 0;
    }
}
__global__ void k_fill(const int* __restrict__ src, const int* __restrict__ dst) {
    int e = blockIdx.x * blockDim.x + threadIdx.x;
    if (e < EE) {
        int d = dst[e];
        int pos = g_rowptr[d] + atomicAdd(&g_deg[d], 1);
        g_col[pos] = src[e];
    }
}

// ---------------- mean aggregation: warp per destination node ----------------
__global__ void k_agg(const float* __restrict__ ext_in, int in_sel) {
    int warp = (blockIdx.x * blockDim.x + threadIdx.x) >> 5;
    int lane = threadIdx.x & 31;
    if (warp >= NN) return;
    const float* hin = (in_sel < 0) ? ext_in : buf_sel(in_sel);
    int s = g_rowptr[warp];
    int e = g_rowptr[warp + 1];
    float4 acc = make_float4(0.f, 0.f, 0.f, 0.f);
    int i = s;
    for (; i + 2 <= e; i += 2) {
        int s0 = g_col[i];
        int s1 = g_col[i + 1];
        float4 v0 = *(const float4*)(hin + (size_t)s0 * DD + lane * 4);
        float4 v1 = *(const float4*)(hin + (size_t)s1 * DD + lane * 4);
        acc.x += v0.x + v1.x; acc.y += v0.y + v1.y;
        acc.z += v0.z + v1.z; acc.w += v0.w + v1.w;
    }
    if (i < e) {
        int s0 = g_col[i];
        float4 v0 = *(const float4*)(hin + (size_t)s0 * DD + lane * 4);
        acc.x += v0.x; acc.y += v0.y; acc.z += v0.z; acc.w += v0.w;
    }
    float iv = g_invdeg[warp];
    acc.x *= iv; acc.y *= iv; acc.z *= iv; acc.w *= iv;
    *(float4*)(g_agg + (size_t)warp * DD + lane * 4) = acc;
}

// ---------------- fp32 -> bf16 hi/lo split ----------------
__device__ __forceinline__ void split2(float a, float b, uint32_t& hi, uint32_t& lo) {
    __nv_bfloat16 ha = __float2bfloat16(a);
    __nv_bfloat16 hb = __float2bfloat16(b);
    __nv_bfloat16 la = __float2bfloat16(a - __bfloat162float(ha));
    __nv_bfloat16 lb = __float2bfloat16(b - __bfloat162float(hb));
    hi = ((uint32_t)__bfloat16_as_ushort(hb) << 16) | __bfloat16_as_ushort(ha);
    lo = ((uint32_t)__bfloat16_as_ushort(lb) << 16) | __bfloat16_as_ushort(la);
}

// W^T hi/lo split: Bmat[n][k] = k<128 ? Wl[k][n] : Wr[k-128][n]
__global__ void k_prep_w(const float* __restrict__ Wl, const float* __restrict__ Wr, int layer) {
    int idx = blockIdx.x * blockDim.x + threadIdx.x;   // over DD*KK/2 pairs
    if (idx >= DD * KK / 2) return;
    int n = idx >> 7;            // 0..127
    int kp = (idx & 127) * 2;    // even k
    float w0 = (kp < 128) ? Wl[kp * 128 + n] : Wr[(kp - 128) * 128 + n];
    int k1 = kp + 1;
    float w1 = (k1 < 128) ? Wl[k1 * 128 + n] : Wr[(k1 - 128) * 128 + n];
    uint32_t hi, lo;
    split2(w0, w1, hi, lo);
    ((uint32_t*)g_Whi[layer])[n * (KK / 2) + (kp >> 1)] = hi;
    ((uint32_t*)g_Wlo[layer])[n * (KK / 2) + (kp >> 1)] = lo;
}

// per layer: A = [agg | x] as bf16 hi/lo, [N, 256]
__global__ void k_convert(const float* __restrict__ ext_x, int x_sel) {
    int t = blockIdx.x * blockDim.x + threadIdx.x;     // over NN*32
    if (t >= NN * 32) return;
    const float* xin = (x_sel < 0) ? ext_x : buf_sel(x_sel);
    int row = t >> 5;
    int q = t & 31;
    float4 a = *(const float4*)(g_agg + (size_t)row * DD + q * 4);
    float4 xv = *(const float4*)(xin + (size_t)row * DD + q * 4);
    uint32_t h0, l0, h1, l1;
    split2(a.x, a.y, h0, l0);
    split2(a.z, a.w, h1, l1);
    *(uint2*)(g_Ahi + (size_t)row * KK + q * 4) = make_uint2(h0, h1);
    *(uint2*)(g_Alo + (size_t)row * KK + q * 4) = make_uint2(l0, l1);
    split2(xv.x, xv.y, h0, l0);
    split2(xv.z, xv.w, h1, l1);
    *(uint2*)(g_Ahi + (size_t)row * KK + 128 + q * 4) = make_uint2(h0, h1);
    *(uint2*)(g_Alo + (size_t)row * KK + 128 + q * 4) = make_uint2(l0, l1);
}

// ---------------- HMMA GEMM: out = relu(A @ W^T + b) ----------------
// mma.sync m16n8k16 bf16, 2-term split: C = Ah*Wh + Ah*Wl + Al*Wh.
// Block 256 thr (8 warps), tile 128x128. Warp tile 32x64 (warps: 4 in M, 2 in N).
__device__ __forceinline__ void mma16816(float* c, const uint32_t* a, const uint32_t* b) {
    asm volatile(
        "mma.sync.aligned.m16n8k16.row.col.f32.bf16.bf16.f32 "
        "{%0,%1,%2,%3}, {%4,%5,%6,%7}, {%8,%9}, {%0,%1,%2,%3};"
        : "+f"(c[0]), "+f"(c[1]), "+f"(c[2]), "+f"(c[3])
        : "r"(a[0]), "r"(a[1]), "r"(a[2]), "r"(a[3]), "r"(b[0]), "r"(b[1]));
}

__global__ void __launch_bounds__(256) k_gemm_hmma(const float* __restrict__ bl,
                                                   int layer, int out_sel) {
    int tid = threadIdx.x;
    int wid = tid >> 5;
    int lane = tid & 31;
    int wm = wid & 3;          // 0..3 -> M offset wm*32
    int wn = wid >> 2;         // 0..1 -> N offset wn*64
    int block_m = blockIdx.x * TM;

    const __nv_bfloat16* Ah = g_Ahi;
    const __nv_bfloat16* Al = g_Alo;
    const __nv_bfloat16* Bh = g_Whi[layer];
    const __nv_bfloat16* Bl = g_Wlo[layer];

    int grp = lane >> 2;       // 0..7
    int quad = lane & 3;       // 0..3
    int kc_off = quad * 2;

    // A row indices for 2 m-subtiles x 2 row-halves, clamped
    int arow[2][2];
#pragma unroll
    for (int mi = 0; mi < 2; ++mi) {
        int r0 = block_m + wm * 32 + mi * 16 + grp;
        int r1 = r0 + 8;
        arow[mi][0] = r0 < NN ? r0 : NN - 1;
        arow[mi][1] = r1 < NN ? r1 : NN - 1;
    }
    // B row (n) indices for 8 n-subtiles
    int brow[8];
#pragma unroll
    for (int ni = 0; ni < 8; ++ni) brow[ni] = wn * 64 + ni * 8 + grp;

    float acc[2][8][4];
#pragma unroll
    for (int mi = 0; mi < 2; ++mi)
#pragma unroll
        for (int ni = 0; ni < 8; ++ni)
#pragma unroll
            for (int r = 0; r < 4; ++r) acc[mi][ni][r] = 0.f;

#pragma unroll 4
    for (int k0 = 0; k0 < KK; k0 += 16) {
        int kc = k0 + kc_off;
        uint32_t ah[2][4], al[2][4];
#pragma unroll
        for (int mi = 0; mi < 2; ++mi) {
            const __nv_bfloat16* p0 = Ah + (size_t)arow[mi][0] * KK + kc;
            const __nv_bfloat16* p1 = Ah + (size_t)arow[mi][1] * KK + kc;
            ah[mi][0] = *(const uint32_t*)p0;
            ah[mi][1] = *(const uint32_t*)p1;
            ah[mi][2] = *(const uint32_t*)(p0 + 8);
            ah[mi][3] = *(const uint32_t*)(p1 + 8);
            const __nv_bfloat16* q0 = Al + (size_t)arow[mi][0] * KK + kc;
            const __nv_bfloat16* q1 = Al + (size_t)arow[mi][1] * KK + kc;
            al[mi][0] = *(const uint32_t*)q0;
            al[mi][1] = *(const uint32_t*)q1;
            al[mi][2] = *(const uint32_t*)(q0 + 8);
            al[mi][3] = *(const uint32_t*)(q1 + 8);
        }
        uint32_t bh[8][2], blo[8][2];
#pragma unroll
        for (int ni = 0; ni < 8; ++ni) {
            const __nv_bfloat16* p = Bh + (size_t)brow[ni] * KK + kc;
            bh[ni][0] = *(const uint32_t*)p;
            bh[ni][1] = *(const uint32_t*)(p + 8);
            const __nv_bfloat16* q = Bl + (size_t)brow[ni] * KK + kc;
            blo[ni][0] = *(const uint32_t*)q;
            blo[ni][1] = *(const uint32_t*)(q + 8);
        }
#pragma unroll
        for (int mi = 0; mi < 2; ++mi)
#pragma unroll
            for (int ni = 0; ni < 8; ++ni) {
                mma16816(acc[mi][ni], ah[mi], bh[ni]);
                mma16816(acc[mi][ni], ah[mi], blo[ni]);
                mma16816(acc[mi][ni], al[mi], bh[ni]);
            }
    }

    // epilogue
    float* outp = buf_sel(out_sel);
#pragma unroll
    for (int mi = 0; mi < 2; ++mi) {
        int r0 = block_m + wm * 32 + mi * 16 + grp;
#pragma unroll
        for (int ni = 0; ni < 8; ++ni) {
            int col = wn * 64 + ni * 8 + quad * 2;
            float b0 = bl[col], b1 = bl[col + 1];
            if (r0 < NN) {
                float2 v;
                v.x = fmaxf(acc[mi][ni][0] + b0, 0.f);
                v.y = fmaxf(acc[mi][ni][1] + b1, 0.f);
                *(float2*)(outp + (size_t)r0 * DD + col) = v;
            }
            if (r0 + 8 < NN) {
                float2 v;
                v.x = fmaxf(acc[mi][ni][2] + b0, 0.f);
                v.y = fmaxf(acc[mi][ni][3] + b1, 0.f);
                *(float2*)(outp + (size_t)(r0 + 8) * DD + col) = v;
            }
        }
    }
}

// ---------------- pooling + roots ----------------
__global__ void k_zero_pool() {
    int i = blockIdx.x * blockDim.x + threadIdx.x;
    if (i < BB * DD) ((int*)g_pool)[i] = 0;
}
__global__ void k_pool(const int* __restrict__ batch) {
    int warp = (blockIdx.x * blockDim.x + threadIdx.x) >> 5;
    int lane = threadIdx.x & 31;
    if (warp >= NN) return;
    int b = batch[warp];
    float4 v = *(const float4*)(g_h1 + (size_t)warp * DD + lane * 4);
    int* p = (int*)g_pool + (size_t)b * DD + lane * 4;
    atomicMax(p + 0, __float_as_int(v.x));
    atomicMax(p + 1, __float_as_int(v.y));
    atomicMax(p + 2, __float_as_int(v.z));
    atomicMax(p + 3, __float_as_int(v.w));
}
__global__ void k_roots(const int* __restrict__ batch) {
    int i = blockIdx.x * blockDim.x + threadIdx.x;
    if (i < NN) {
        int b = batch[i];
        if (i == 0 || batch[i - 1] != b) g_root[b] = i;
    }
}

// ---------------- per-graph MLP head ----------------
__global__ void __launch_bounds__(256) k_head(const float* __restrict__ x,
                                              const float* __restrict__ Wf1, const float* __restrict__ bf1,
                                              const float* __restrict__ Wf2, const float* __restrict__ bf2,
                                              const float* __restrict__ Wsm, const float* __restrict__ bsm,
                                              const float* __restrict__ Wnews, const float* __restrict__ bnews,
                                              const float* __restrict__ Wcat, const float* __restrict__ bcat,
                                              float* __restrict__ out) {
    int b = blockIdx.x;
    int t = threadIdx.x;
    __shared__ float p[128], xr[128], t1[256], t2[128], sres[4];
    if (t < 128) {
        p[t] = g_pool[(size_t)b * DD + t];
        xr[t] = x[(size_t)g_root[b] * DD + t];
    }
    __syncthreads();
    {
        float acc = bf1[t];
#pragma unroll 4
        for (int k = 0; k < 128; k++) acc += p[k] * Wf1[k * 256 + t];
        t1[t] = fmaxf(acc, 0.f);
    }
    __syncthreads();
    if (t < 128) {
        float acc = bf2[t];
#pragma unroll 4
        for (int k = 0; k < 256; k++) acc += t1[k] * Wf2[k * 128 + t];
        t2[t] = fmaxf(acc, 0.f);
    }
    __syncthreads();
    if (t < 2) {
        float acc = bsm[t];
        for (int k = 0; k < 128; k++) acc += t2[k] * Wsm[k * 2 + t];
        sres[t] = fmaxf(acc, 0.f);
        float a2 = bnews[t];
        for (int k = 0; k < 128; k++) a2 += xr[k] * Wnews[k * 2 + t];
        sres[2 + t] = fmaxf(a2, 0.f);
    }
    __syncthreads();
    if (t == 0) {
        float o = bcat[0];
        for (int k = 0; k < 4; k++) o += sres[k] * Wcat[k];
        out[b] = 1.f / (1.f + expf(-o));
    }
}

// ---------------- launch ----------------
extern "C" void kernel_launch(void* const* d_in, const int* in_sizes, int n_in,
                              void* d_out, int out_size) {
    const float* x     = (const float*)d_in[0];
    const int*   ei    = (const int*)d_in[1];
    const int*   src   = ei;
    const int*   dst   = ei + EE;
    const int*   batch = (const int*)d_in[2];
    const float* Wl1 = (const float*)d_in[3];
    const float* Wr1 = (const float*)d_in[4];
    const float* bl1 = (const float*)d_in[5];
    const float* Wl2 = (const float*)d_in[6];
    const float* Wr2 = (const float*)d_in[7];
    const float* bl2 = (const float*)d_in[8];
    const float* Wl3 = (const float*)d_in[9];
    const float* Wr3 = (const float*)d_in[10];
    const float* bl3 = (const float*)d_in[11];
    const float* Wf1 = (const float*)d_in[12];
    const float* bf1 = (const float*)d_in[13];
    const float* Wf2 = (const float*)d_in[14];
    const float* bf2 = (const float*)d_in[15];
    const float* Wsm = (const float*)d_in[16];
    const float* bsm = (const float*)d_in[17];
    const float* Wnews = (const float*)d_in[18];
    const float* bnews = (const float*)d_in[19];
    const float* Wcat = (const float*)d_in[20];
    const float* bcat = (const float*)d_in[21];
    float* out = (float*)d_out;

    const int TB = 256;
    int gN = (NN + TB - 1) / TB;
    int gE = (EE + TB - 1) / TB;
    int gWarpN = (NN * 32 + TB - 1) / TB;
    int gPrep = (DD * KK / 2 + TB - 1) / TB;

    k_prep_w<<<gPrep, TB>>>(Wl1, Wr1, 0);
    k_prep_w<<<gPrep, TB>>>(Wl2, Wr2, 1);
    k_prep_w<<<gPrep, TB>>>(Wl3, Wr3, 2);

    k_zero_deg<<<gN, TB>>>();
    k_count<<<gE, TB>>>(dst);
    k_scan<<<1, 1024>>>();
    k_invdeg_reset<<<gN, TB>>>();
    k_fill<<<gE, TB>>>(src, dst);

    // layer 1: x -> h1
    k_agg<<<gWarpN, TB>>>(x, -1);
    k_convert<<<gWarpN, TB>>>(x, -1);
    k_gemm_hmma<<<GEMM_BLOCKS, 256>>>(bl1, 0, 1);
    // layer 2: h1 -> h2
    k_agg<<<gWarpN, TB>>>(nullptr, 1);
    k_convert<<<gWarpN, TB>>>(nullptr, 1);
    k_gemm_hmma<<<GEMM_BLOCKS, 256>>>(bl2, 1, 2);
    // layer 3: h2 -> h1
    k_agg<<<gWarpN, TB>>>(nullptr, 2);
    k_convert<<<gWarpN, TB>>>(nullptr, 2);
    k_gemm_hmma<<<GEMM_BLOCKS, 256>>>(bl3, 2, 1);

    k_zero_pool<<<(BB * DD + TB - 1) / TB, TB>>>();
    k_pool<<<gWarpN, TB>>>(batch);
    k_roots<<<gN, TB>>>(batch);
    k_head<<<BB, TB>>>(x, Wf1, bf1, Wf2, bf2, Wsm, bsm, Wnews, bnews, Wcat, bcat, out);
}

// round 4
// speedup vs baseline: 1.6121x; 1.1348x over previous
#include <cuda_runtime.h>
#include <cuda_bf16.h>
#include <math.h>
#include <stdint.h>

#define NN 50000
#define EE 800000
#define BB 512
#define DD 128
#define KK 256
#define TM 128
#define GEMM_BLOCKS ((NN + TM - 1) / TM)   // 391

// ---------------- scratch (static device globals; no allocation) ----------------
__device__ float g_h1[NN * DD];
__device__ float g_h2[NN * DD];
__device__ __nv_bfloat16 g_Ahi[NN * KK];      // [agg_split | h_split]
__device__ __nv_bfloat16 g_Alo[NN * KK];
__device__ __nv_bfloat16 g_Whi[3][DD * KK];   // W^T: row n (out col), col k
__device__ __nv_bfloat16 g_Wlo[3][DD * KK];
__device__ float g_pool[BB * DD];
__device__ float g_invdeg[NN];
__device__ int   g_deg[NN];
__device__ int   g_rowptr[NN + 1];
__device__ int   g_col[EE];
__device__ int   g_root[BB];

__device__ __forceinline__ float* hbuf(int i) { return i == 2 ? g_h2 : g_h1; }

// ---------------- fp32 -> bf16 hi/lo split ----------------
__device__ __forceinline__ void split2(float a, float b, uint32_t& hi, uint32_t& lo) {
    __nv_bfloat16 ha = __float2bfloat16(a);
    __nv_bfloat16 hb = __float2bfloat16(b);
    __nv_bfloat16 la = __float2bfloat16(a - __bfloat162float(ha));
    __nv_bfloat16 lb = __float2bfloat16(b - __bfloat162float(hb));
    hi = ((uint32_t)__bfloat16_as_ushort(hb) << 16) | __bfloat16_as_ushort(ha);
    lo = ((uint32_t)__bfloat16_as_ushort(lb) << 16) | __bfloat16_as_ushort(la);
}

// ---------------- init: zero deg + pool ----------------
__global__ void k_init() {
    int i = blockIdx.x * blockDim.x + threadIdx.x;   // 65536 threads
    if (i < NN) g_deg[i] = 0;
    if (i < BB * DD) ((int*)g_pool)[i] = 0;          // 0 bits == +0.0f
}

__global__ void k_count(const int* __restrict__ dst) {
    int e = blockIdx.x * blockDim.x + threadIdx.x;
    if (e < EE) atomicAdd(&g_deg[dst[e]], 1);
}

// warp-shuffle exclusive scan over g_deg -> g_rowptr
__global__ void k_scan() {
    __shared__ int wsum[32];
    __shared__ int carry;
    int tid = threadIdx.x;
    int warp = tid >> 5, lane = tid & 31;
    if (tid == 0) carry = 0;
    __syncthreads();
    for (int base = 0; base < NN; base += 1024) {
        int i = base + tid;
        int v = (i < NN) ? g_deg[i] : 0;
        int s = v;
#pragma unroll
        for (int off = 1; off < 32; off <<= 1) {
            int t = __shfl_up_sync(0xFFFFFFFFu, s, off);
            if (lane >= off) s += t;
        }
        if (lane == 31) wsum[warp] = s;
        __syncthreads();
        if (warp == 0) {
            int w = wsum[lane];
#pragma unroll
            for (int off = 1; off < 32; off <<= 1) {
                int t = __shfl_up_sync(0xFFFFFFFFu, w, off);
                if (lane >= off) w += t;
            }
            wsum[lane] = w;
        }
        __syncthreads();
        int off = carry + (warp ? wsum[warp - 1] : 0);
        if (i < NN) g_rowptr[i] = off + s - v;
        __syncthreads();
        if (tid == 0) carry += wsum[31];
        __syncthreads();
    }
    if (tid == 0) g_rowptr[NN] = carry;
}

// invdeg + cursor reset + roots (fused)
__global__ void k_invdeg_roots(const int* __restrict__ batch) {
    int i = blockIdx.x * blockDim.x + threadIdx.x;
    if (i < NN) {
        int d = g_deg[i];
        g_invdeg[i] = 1.0f / (float)(d > 1 ? d : 1);
        g_deg[i] = 0;
        int b = batch[i];
        if (i == 0 || batch[i - 1] != b) g_root[b] = i;
    }
}

__global__ void k_fill(const int* __restrict__ src, const int* __restrict__ dst) {
    int e = blockIdx.x * blockDim.x + threadIdx.x;
    if (e < EE) {
        int d = dst[e];
        int pos = g_rowptr[d] + atomicAdd(&g_deg[d], 1);
        g_col[pos] = src[e];
    }
}

// ---------------- mean aggregation: warp per node, writes bf16 split to A[:,0:128] ----------------
__global__ void __launch_bounds__(256) k_agg_split(const float* __restrict__ ext_in, int in_sel) {
    int warp = (blockIdx.x * blockDim.x + threadIdx.x) >> 5;
    int lane = threadIdx.x & 31;
    if (warp >= NN) return;
    const float* hin = (in_sel < 0) ? ext_in : hbuf(in_sel);
    int s = g_rowptr[warp];
    int e = g_rowptr[warp + 1];
    float4 a0 = make_float4(0.f, 0.f, 0.f, 0.f);
    float4 a1 = a0, a2 = a0, a3 = a0;
    int i = s;
    for (; i + 4 <= e; i += 4) {
        int c0 = g_col[i], c1 = g_col[i + 1], c2 = g_col[i + 2], c3 = g_col[i + 3];
        float4 v0 = *(const float4*)(hin + (size_t)c0 * DD + lane * 4);
        float4 v1 = *(const float4*)(hin + (size_t)c1 * DD + lane * 4);
        float4 v2 = *(const float4*)(hin + (size_t)c2 * DD + lane * 4);
        float4 v3 = *(const float4*)(hin + (size_t)c3 * DD + lane * 4);
        a0.x += v0.x; a0.y += v0.y; a0.z += v0.z; a0.w += v0.w;
        a1.x += v1.x; a1.y += v1.y; a1.z += v1.z; a1.w += v1.w;
        a2.x += v2.x; a2.y += v2.y; a2.z += v2.z; a2.w += v2.w;
        a3.x += v3.x; a3.y += v3.y; a3.z += v3.z; a3.w += v3.w;
    }
    for (; i < e; ++i) {
        int c0 = g_col[i];
        float4 v0 = *(const float4*)(hin + (size_t)c0 * DD + lane * 4);
        a0.x += v0.x; a0.y += v0.y; a0.z += v0.z; a0.w += v0.w;
    }
    float iv = g_invdeg[warp];
    float4 m;
    m.x = (a0.x + a1.x + a2.x + a3.x) * iv;
    m.y = (a0.y + a1.y + a2.y + a3.y) * iv;
    m.z = (a0.z + a1.z + a2.z + a3.z) * iv;
    m.w = (a0.w + a1.w + a2.w + a3.w) * iv;
    uint32_t h0, l0, h1, l1;
    split2(m.x, m.y, h0, l0);
    split2(m.z, m.w, h1, l1);
    *(uint2*)(g_Ahi + (size_t)warp * KK + lane * 4) = make_uint2(h0, h1);
    *(uint2*)(g_Alo + (size_t)warp * KK + lane * 4) = make_uint2(l0, l1);
}

// x (external fp32) -> bf16 split into A[:,128:256] (layer-1 only)
__global__ void k_xsplit(const float* __restrict__ x) {
    int t = blockIdx.x * blockDim.x + threadIdx.x;
    if (t >= NN * 32) return;
    int row = t >> 5;
    int q = t & 31;
    float4 xv = *(const float4*)(x + (size_t)row * DD + q * 4);
    uint32_t h0, l0, h1, l1;
    split2(xv.x, xv.y, h0, l0);
    split2(xv.z, xv.w, h1, l1);
    *(uint2*)(g_Ahi + (size_t)row * KK + 128 + q * 4) = make_uint2(h0, h1);
    *(uint2*)(g_Alo + (size_t)row * KK + 128 + q * 4) = make_uint2(l0, l1);
}

// W^T hi/lo split for all 3 layers in one launch
__global__ void k_prep_w(const float* __restrict__ Wl1, const float* __restrict__ Wr1,
                         const float* __restrict__ Wl2, const float* __restrict__ Wr2,
                         const float* __restrict__ Wl3, const float* __restrict__ Wr3) {
    int gidx = blockIdx.x * blockDim.x + threadIdx.x;
    const int PER = DD * KK / 2;                    // 16384 pairs per layer
    int layer = gidx / PER;
    if (layer >= 3) return;
    int idx = gidx - layer * PER;
    const float* Wl = layer == 0 ? Wl1 : (layer == 1 ? Wl2 : Wl3);
    const float* Wr = layer == 0 ? Wr1 : (layer == 1 ? Wr2 : Wr3);
    int n = idx >> 7;
    int kp = (idx & 127) * 2;
    float w0 = (kp < 128) ? Wl[kp * 128 + n] : Wr[(kp - 128) * 128 + n];
    int k1 = kp + 1;
    float w1 = (k1 < 128) ? Wl[k1 * 128 + n] : Wr[(k1 - 128) * 128 + n];
    uint32_t hi, lo;
    split2(w0, w1, hi, lo);
    ((uint32_t*)g_Whi[layer])[n * (KK / 2) + (kp >> 1)] = hi;
    ((uint32_t*)g_Wlo[layer])[n * (KK / 2) + (kp >> 1)] = lo;
}

// ---------------- HMMA GEMM: h = relu(A @ W^T + b); optionally also write bf16 split of h ----------------
__device__ __forceinline__ void mma16816(float* c, const uint32_t* a, const uint32_t* b) {
    asm volatile(
        "mma.sync.aligned.m16n8k16.row.col.f32.bf16.bf16.f32 "
        "{%0,%1,%2,%3}, {%4,%5,%6,%7}, {%8,%9}, {%0,%1,%2,%3};"
        : "+f"(c[0]), "+f"(c[1]), "+f"(c[2]), "+f"(c[3])
        : "r"(a[0]), "r"(a[1]), "r"(a[2]), "r"(a[3]), "r"(b[0]), "r"(b[1]));
}

__global__ void __launch_bounds__(256) k_gemm_hmma(const float* __restrict__ bl,
                                                   int layer, int out_sel, int write_split) {
    int tid = threadIdx.x;
    int wid = tid >> 5;
    int lane = tid & 31;
    int wm = wid & 3;
    int wn = wid >> 2;
    int block_m = blockIdx.x * TM;

    const __nv_bfloat16* Ah = g_Ahi;
    const __nv_bfloat16* Al = g_Alo;
    const __nv_bfloat16* Bh = g_Whi[layer];
    const __nv_bfloat16* Bl = g_Wlo[layer];

    int grp = lane >> 2;
    int quad = lane & 3;
    int kc_off = quad * 2;

    int arow[2][2];
#pragma unroll
    for (int mi = 0; mi < 2; ++mi) {
        int r0 = block_m + wm * 32 + mi * 16 + grp;
        int r1 = r0 + 8;
        arow[mi][0] = r0 < NN ? r0 : NN - 1;
        arow[mi][1] = r1 < NN ? r1 : NN - 1;
    }
    int brow[8];
#pragma unroll
    for (int ni = 0; ni < 8; ++ni) brow[ni] = wn * 64 + ni * 8 + grp;

    float acc[2][8][4];
#pragma unroll
    for (int mi = 0; mi < 2; ++mi)
#pragma unroll
        for (int ni = 0; ni < 8; ++ni)
#pragma unroll
            for (int r = 0; r < 4; ++r) acc[mi][ni][r] = 0.f;

#pragma unroll 4
    for (int k0 = 0; k0 < KK; k0 += 16) {
        int kc = k0 + kc_off;
        uint32_t ah[2][4], al[2][4];
#pragma unroll
        for (int mi = 0; mi < 2; ++mi) {
            const __nv_bfloat16* p0 = Ah + (size_t)arow[mi][0] * KK + kc;
            const __nv_bfloat16* p1 = Ah + (size_t)arow[mi][1] * KK + kc;
            ah[mi][0] = *(const uint32_t*)p0;
            ah[mi][1] = *(const uint32_t*)p1;
            ah[mi][2] = *(const uint32_t*)(p0 + 8);
            ah[mi][3] = *(const uint32_t*)(p1 + 8);
            const __nv_bfloat16* q0 = Al + (size_t)arow[mi][0] * KK + kc;
            const __nv_bfloat16* q1 = Al + (size_t)arow[mi][1] * KK + kc;
            al[mi][0] = *(const uint32_t*)q0;
            al[mi][1] = *(const uint32_t*)q1;
            al[mi][2] = *(const uint32_t*)(q0 + 8);
            al[mi][3] = *(const uint32_t*)(q1 + 8);
        }
        uint32_t bh[8][2], blo[8][2];
#pragma unroll
        for (int ni = 0; ni < 8; ++ni) {
            const __nv_bfloat16* p = Bh + (size_t)brow[ni] * KK + kc;
            bh[ni][0] = *(const uint32_t*)p;
            bh[ni][1] = *(const uint32_t*)(p + 8);
            const __nv_bfloat16* q = Bl + (size_t)brow[ni] * KK + kc;
            blo[ni][0] = *(const uint32_t*)q;
            blo[ni][1] = *(const uint32_t*)(q + 8);
        }
#pragma unroll
        for (int mi = 0; mi < 2; ++mi)
#pragma unroll
            for (int ni = 0; ni < 8; ++ni) {
                mma16816(acc[mi][ni], ah[mi], bh[ni]);
                mma16816(acc[mi][ni], ah[mi], blo[ni]);
                mma16816(acc[mi][ni], al[mi], bh[ni]);
            }
    }

    // epilogue: fp32 h + optional bf16 split of h into A[:,128:256]
    float* outp = hbuf(out_sel);
#pragma unroll
    for (int mi = 0; mi < 2; ++mi) {
        int r0 = block_m + wm * 32 + mi * 16 + grp;
#pragma unroll
        for (int ni = 0; ni < 8; ++ni) {
            int col = wn * 64 + ni * 8 + quad * 2;
            float b0 = bl[col], b1 = bl[col + 1];
            if (r0 < NN) {
                float2 v;
                v.x = fmaxf(acc[mi][ni][0] + b0, 0.f);
                v.y = fmaxf(acc[mi][ni][1] + b1, 0.f);
                *(float2*)(outp + (size_t)r0 * DD + col) = v;
                if (write_split) {
                    uint32_t hi, lo;
                    split2(v.x, v.y, hi, lo);
                    *(uint32_t*)(g_Ahi + (size_t)r0 * KK + 128 + col) = hi;
                    *(uint32_t*)(g_Alo + (size_t)r0 * KK + 128 + col) = lo;
                }
            }
            if (r0 + 8 < NN) {
                float2 v;
                v.x = fmaxf(acc[mi][ni][2] + b0, 0.f);
                v.y = fmaxf(acc[mi][ni][3] + b1, 0.f);
                *(float2*)(outp + (size_t)(r0 + 8) * DD + col) = v;
                if (write_split) {
                    uint32_t hi, lo;
                    split2(v.x, v.y, hi, lo);
                    *(uint32_t*)(g_Ahi + (size_t)(r0 + 8) * KK + 128 + col) = hi;
                    *(uint32_t*)(g_Alo + (size_t)(r0 + 8) * KK + 128 + col) = lo;
                }
            }
        }
    }
}

// ---------------- pooling: block of 128 threads, 64 nodes, flush on graph change ----------------
#define POOL_NODES 64
__global__ void __launch_bounds__(128) k_pool2(const int* __restrict__ batch) {
    int n0 = blockIdx.x * POOL_NODES;
    int col = threadIdx.x;
    if (n0 >= NN) return;
    int nend = n0 + POOL_NODES; if (nend > NN) nend = NN;
    int cur = batch[n0];
    float m = 0.f;
    for (int n = n0; n < nend; ++n) {
        int b = batch[n];
        if (b != cur) {
            atomicMax((int*)g_pool + (size_t)cur * DD + col, __float_as_int(m));
            m = 0.f;
            cur = b;
        }
        float v = g_h1[(size_t)n * DD + col];
        m = fmaxf(m, v);
    }
    atomicMax((int*)g_pool + (size_t)cur * DD + col, __float_as_int(m));
}

// ---------------- per-graph MLP head ----------------
__global__ void __launch_bounds__(256) k_head(const float* __restrict__ x,
                                              const float* __restrict__ Wf1, const float* __restrict__ bf1,
                                              const float* __restrict__ Wf2, const float* __restrict__ bf2,
                                              const float* __restrict__ Wsm, const float* __restrict__ bsm,
                                              const float* __restrict__ Wnews, const float* __restrict__ bnews,
                                              const float* __restrict__ Wcat, const float* __restrict__ bcat,
                                              float* __restrict__ out) {
    int b = blockIdx.x;
    int t = threadIdx.x;
    __shared__ float p[128], xr[128], t1[256], t2[128], sres[4];
    if (t < 128) {
        p[t] = g_pool[(size_t)b * DD + t];
        xr[t] = x[(size_t)g_root[b] * DD + t];
    }
    __syncthreads();
    {
        float acc = bf1[t];
#pragma unroll 4
        for (int k = 0; k < 128; k++) acc += p[k] * Wf1[k * 256 + t];
        t1[t] = fmaxf(acc, 0.f);
    }
    __syncthreads();
    if (t < 128) {
        float acc = bf2[t];
#pragma unroll 4
        for (int k = 0; k < 256; k++) acc += t1[k] * Wf2[k * 128 + t];
        t2[t] = fmaxf(acc, 0.f);
    }
    __syncthreads();
    if (t < 2) {
        float acc = bsm[t];
        for (int k = 0; k < 128; k++) acc += t2[k] * Wsm[k * 2 + t];
        sres[t] = fmaxf(acc, 0.f);
        float a2 = bnews[t];
        for (int k = 0; k < 128; k++) a2 += xr[k] * Wnews[k * 2 + t];
        sres[2 + t] = fmaxf(a2, 0.f);
    }
    __syncthreads();
    if (t == 0) {
        float o = bcat[0];
        for (int k = 0; k < 4; k++) o += sres[k] * Wcat[k];
        out[b] = 1.f / (1.f + expf(-o));
    }
}

// ---------------- launch ----------------
extern "C" void kernel_launch(void* const* d_in, const int* in_sizes, int n_in,
                              void* d_out, int out_size) {
    const float* x     = (const float*)d_in[0];
    const int*   ei    = (const int*)d_in[1];
    const int*   src   = ei;
    const int*   dst   = ei + EE;
    const int*   batch = (const int*)d_in[2];
    const float* Wl1 = (const float*)d_in[3];
    const float* Wr1 = (const float*)d_in[4];
    const float* bl1 = (const float*)d_in[5];
    const float* Wl2 = (const float*)d_in[6];
    const float* Wr2 = (const float*)d_in[7];
    const float* bl2 = (const float*)d_in[8];
    const float* Wl3 = (const float*)d_in[9];
    const float* Wr3 = (const float*)d_in[10];
    const float* bl3 = (const float*)d_in[11];
    const float* Wf1 = (const float*)d_in[12];
    const float* bf1 = (const float*)d_in[13];
    const float* Wf2 = (const float*)d_in[14];
    const float* bf2 = (const float*)d_in[15];
    const float* Wsm = (const float*)d_in[16];
    const float* bsm = (const float*)d_in[17];
    const float* Wnews = (const float*)d_in[18];
    const float* bnews = (const float*)d_in[19];
    const float* Wcat = (const float*)d_in[20];
    const float* bcat = (const float*)d_in[21];
    float* out = (float*)d_out;

    const int TB = 256;
    int gE = (EE + TB - 1) / TB;
    int gN = (NN + TB - 1) / TB;
    int gWarpN = (NN * 32 + TB - 1) / TB;
    int gPrep = (3 * DD * KK / 2 + TB - 1) / TB;

    // CSR build (ordered so the ncu-captured 6th launch is k_agg_split)
    k_init<<<256, TB>>>();
    k_count<<<gE, TB>>>(dst);
    k_scan<<<1, 1024>>>();
    k_invdeg_roots<<<gN, TB>>>(batch);
    k_fill<<<gE, TB>>>(src, dst);

    // layer 1
    k_agg_split<<<gWarpN, TB>>>(x, -1);          // <- profiled launch
    k_prep_w<<<gPrep, TB>>>(Wl1, Wr1, Wl2, Wr2, Wl3, Wr3);
    k_xsplit<<<gWarpN, TB>>>(x);
    k_gemm_hmma<<<GEMM_BLOCKS, 256>>>(bl1, 0, 1, 1);
    // layer 2
    k_agg_split<<<gWarpN, TB>>>(nullptr, 1);
    k_gemm_hmma<<<GEMM_BLOCKS, 256>>>(bl2, 1, 2, 1);
    // layer 3
    k_agg_split<<<gWarpN, TB>>>(nullptr, 2);
    k_gemm_hmma<<<GEMM_BLOCKS, 256>>>(bl3, 2, 1, 0);

    // pool + head
    k_pool2<<<(NN + POOL_NODES - 1) / POOL_NODES, 128>>>(batch);
    k_head<<<BB, TB>>>(x, Wf1, bf1, Wf2, bf2, Wsm, bsm, Wnews, bnews, Wcat, bcat, out);
}

// round 6
// speedup vs baseline: 1.8269x; 1.1332x over previous
#include <cuda_runtime.h>
#include <cuda_bf16.h>
#include <math.h>
#include <stdint.h>

#define NN 50000
#define EE 800000
#define BB 512
#define DD 128
#define KK 256
#define TM 128
#define GEMM_BLOCKS ((NN + TM - 1) / TM)   // 391

// ---------------- scratch (static device globals; no allocation) ----------------
__device__ float g_h1[NN * DD];
__device__ float g_h2[NN * DD];
// frag-packed bf16 operand storage: per row, 128 uint32 (= 256 bf16 as 128 col-pairs,
// permuted within each 16-col k-group so mma fragment halves are contiguous 8B)
__device__ uint32_t g_Ahi[NN * 128];
__device__ uint32_t g_Alo[NN * 128];
__device__ uint32_t g_Whi[3][DD * 128];
__device__ uint32_t g_Wlo[3][DD * 128];
__device__ float g_pool[BB * DD];
__device__ float g_invdeg[NN];
__device__ int   g_deg[NN];
__device__ int   g_rowptr[NN + 1];
__device__ int   g_col[EE];
__device__ int   g_root[BB];

__device__ __forceinline__ float* hbuf(int i) { return i == 2 ? g_h2 : g_h1; }

// packed uint32 index (within a 128-uint32 row) for column-pair index `pair` (0..127)
__device__ __forceinline__ int pk_idx(int pair) {
    int g = pair >> 3, pg = pair & 7;
    return g * 8 + ((pg & 3) << 1) + (pg >> 2);
}

// ---------------- fp32 -> bf16 hi/lo split ----------------
__device__ __forceinline__ void split2(float a, float b, uint32_t& hi, uint32_t& lo) {
    __nv_bfloat16 ha = __float2bfloat16(a);
    __nv_bfloat16 hb = __float2bfloat16(b);
    __nv_bfloat16 la = __float2bfloat16(a - __bfloat162float(ha));
    __nv_bfloat16 lb = __float2bfloat16(b - __bfloat162float(hb));
    hi = ((uint32_t)__bfloat16_as_ushort(hb) << 16) | __bfloat16_as_ushort(ha);
    lo = ((uint32_t)__bfloat16_as_ushort(lb) << 16) | __bfloat16_as_ushort(la);
}

// ---------------- init: zero deg + pool ----------------
__global__ void k_init() {
    int i = blockIdx.x * blockDim.x + threadIdx.x;
    if (i < NN) g_deg[i] = 0;
    if (i < BB * DD) ((int*)g_pool)[i] = 0;          // 0 bits == +0.0f
}

__global__ void k_count(const int* __restrict__ dst) {
    int e = blockIdx.x * blockDim.x + threadIdx.x;
    if (e < EE) atomicAdd(&g_deg[dst[e]], 1);
}

// exclusive scan + invdeg + cursor reset + roots, single block
__global__ void k_scan_fused(const int* __restrict__ batch) {
    __shared__ int wsum[32];
    __shared__ int carry;
    int tid = threadIdx.x;
    int warp = tid >> 5, lane = tid & 31;
    if (tid == 0) carry = 0;
    __syncthreads();
    for (int base = 0; base < NN; base += 1024) {
        int i = base + tid;
        int v = (i < NN) ? g_deg[i] : 0;
        int s = v;
#pragma unroll
        for (int off = 1; off < 32; off <<= 1) {
            int t = __shfl_up_sync(0xFFFFFFFFu, s, off);
            if (lane >= off) s += t;
        }
        if (lane == 31) wsum[warp] = s;
        __syncthreads();
        if (warp == 0) {
            int w = wsum[lane];
#pragma unroll
            for (int off = 1; off < 32; off <<= 1) {
                int t = __shfl_up_sync(0xFFFFFFFFu, w, off);
                if (lane >= off) w += t;
            }
            wsum[lane] = w;
        }
        __syncthreads();
        int off = carry + (warp ? wsum[warp - 1] : 0);
        if (i < NN) {
            g_rowptr[i] = off + s - v;
            g_invdeg[i] = 1.0f / (float)(v > 1 ? v : 1);
            g_deg[i] = 0;                          // reuse as fill cursor
            int b = batch[i];
            if (i == 0 || batch[i - 1] != b) g_root[b] = i;
        }
        __syncthreads();
        if (tid == 0) carry += wsum[31];
        __syncthreads();
    }
    if (tid == 0) g_rowptr[NN] = carry;
}

__global__ void k_fill(const int* __restrict__ src, const int* __restrict__ dst) {
    int e = blockIdx.x * blockDim.x + threadIdx.x;
    if (e < EE) {
        int d = dst[e];
        int pos = g_rowptr[d] + atomicAdd(&g_deg[d], 1);
        g_col[pos] = src[e];
    }
}

// ---------------- mean aggregation: warp per node, frag-packed bf16 split output ----------------
__global__ void __launch_bounds__(256) k_agg_split(const float* __restrict__ ext_in,
                                                   int in_sel, int do_x) {
    int warp = (blockIdx.x * blockDim.x + threadIdx.x) >> 5;
    int lane = threadIdx.x & 31;
    if (warp >= NN) return;
    const float* hin = (in_sel < 0) ? ext_in : hbuf(in_sel);
    int s = g_rowptr[warp];
    int e = g_rowptr[warp + 1];
    float4 a0 = make_float4(0.f, 0.f, 0.f, 0.f);
    float4 a1 = a0, a2 = a0, a3 = a0;
    int i = s;
    for (; i + 4 <= e; i += 4) {
        int c0 = g_col[i], c1 = g_col[i + 1], c2 = g_col[i + 2], c3 = g_col[i + 3];
        float4 v0 = *(const float4*)(hin + (size_t)c0 * DD + lane * 4);
        float4 v1 = *(const float4*)(hin + (size_t)c1 * DD + lane * 4);
        float4 v2 = *(const float4*)(hin + (size_t)c2 * DD + lane * 4);
        float4 v3 = *(const float4*)(hin + (size_t)c3 * DD + lane * 4);
        a0.x += v0.x; a0.y += v0.y; a0.z += v0.z; a0.w += v0.w;
        a1.x += v1.x; a1.y += v1.y; a1.z += v1.z; a1.w += v1.w;
        a2.x += v2.x; a2.y += v2.y; a2.z += v2.z; a2.w += v2.w;
        a3.x += v3.x; a3.y += v3.y; a3.z += v3.z; a3.w += v3.w;
    }
    for (; i < e; ++i) {
        int c0 = g_col[i];
        float4 v0 = *(const float4*)(hin + (size_t)c0 * DD + lane * 4);
        a0.x += v0.x; a0.y += v0.y; a0.z += v0.z; a0.w += v0.w;
    }
    float iv = g_invdeg[warp];
    float4 m;
    m.x = (a0.x + a1.x + a2.x + a3.x) * iv;
    m.y = (a0.y + a1.y + a2.y + a3.y) * iv;
    m.z = (a0.z + a1.z + a2.z + a3.z) * iv;
    m.w = (a0.w + a1.w + a2.w + a3.w) * iv;
    uint32_t h0, l0, h1, l1;
    split2(m.x, m.y, h0, l0);
    split2(m.z, m.w, h1, l1);
    int p0 = lane * 2, p1 = lane * 2 + 1;
    uint32_t* rh = g_Ahi + (size_t)warp * 128;
    uint32_t* rl = g_Alo + (size_t)warp * 128;
    rh[pk_idx(p0)] = h0; rh[pk_idx(p1)] = h1;
    rl[pk_idx(p0)] = l0; rl[pk_idx(p1)] = l1;
    if (do_x) {   // layer 1: also split own x row into cols 128:256
        float4 xv = *(const float4*)(ext_in + (size_t)warp * DD + lane * 4);
        split2(xv.x, xv.y, h0, l0);
        split2(xv.z, xv.w, h1, l1);
        rh[pk_idx(64 + p0)] = h0; rh[pk_idx(64 + p1)] = h1;
        rl[pk_idx(64 + p0)] = l0; rl[pk_idx(64 + p1)] = l1;
    }
}

// W^T hi/lo split for all 3 layers, frag-packed
__global__ void k_prep_w(const float* __restrict__ Wl1, const float* __restrict__ Wr1,
                         const float* __restrict__ Wl2, const float* __restrict__ Wr2,
                         const float* __restrict__ Wl3, const float* __restrict__ Wr3) {
    int gidx = blockIdx.x * blockDim.x + threadIdx.x;
    const int PER = DD * KK / 2;                    // 16384 pairs per layer
    int layer = gidx / PER;
    if (layer >= 3) return;
    int idx = gidx - layer * PER;
    const float* Wl = layer == 0 ? Wl1 : (layer == 1 ? Wl2 : Wl3);
    const float* Wr = layer == 0 ? Wr1 : (layer == 1 ? Wr2 : Wr3);
    int n = idx >> 7;
    int kp = (idx & 127) * 2;
    float w0 = (kp < 128) ? Wl[kp * 128 + n] : Wr[(kp - 128) * 128 + n];
    int k1 = kp + 1;
    float w1 = (k1 < 128) ? Wl[k1 * 128 + n] : Wr[(k1 - 128) * 128 + n];
    uint32_t hi, lo;
    split2(w0, w1, hi, lo);
    int pidx = pk_idx(kp >> 1);
    g_Whi[layer][n * 128 + pidx] = hi;
    g_Wlo[layer][n * 128 + pidx] = lo;
}

// ---------------- HMMA GEMM, frag-packed uint2 loads ----------------
__device__ __forceinline__ void mma16816(float* c, const uint32_t* a, const uint32_t* b) {
    asm volatile(
        "mma.sync.aligned.m16n8k16.row.col.f32.bf16.bf16.f32 "
        "{%0,%1,%2,%3}, {%4,%5,%6,%7}, {%8,%9}, {%0,%1,%2,%3};"
        : "+f"(c[0]), "+f"(c[1]), "+f"(c[2]), "+f"(c[3])
        : "r"(a[0]), "r"(a[1]), "r"(a[2]), "r"(a[3]), "r"(b[0]), "r"(b[1]));
}

__global__ void __launch_bounds__(256) k_gemm_hmma(const float* __restrict__ bl,
                                                   int layer, int out_sel, int write_split) {
    int tid = threadIdx.x;
    int wid = tid >> 5;
    int lane = tid & 31;
    int wm = wid & 3;
    int wn = wid >> 2;
    int block_m = blockIdx.x * TM;

    const uint32_t* Bh = g_Whi[layer];
    const uint32_t* Bl = g_Wlo[layer];

    int grp = lane >> 2;
    int quad = lane & 3;

    int arow[2][2];
#pragma unroll
    for (int mi = 0; mi < 2; ++mi) {
        int r0 = block_m + wm * 32 + mi * 16 + grp;
        int r1 = r0 + 8;
        arow[mi][0] = r0 < NN ? r0 : NN - 1;
        arow[mi][1] = r1 < NN ? r1 : NN - 1;
    }
    int brow[8];
#pragma unroll
    for (int ni = 0; ni < 8; ++ni) brow[ni] = wn * 64 + ni * 8 + grp;

    float acc[2][8][4];
#pragma unroll
    for (int mi = 0; mi < 2; ++mi)
#pragma unroll
        for (int ni = 0; ni < 8; ++ni)
#pragma unroll
            for (int r = 0; r < 4; ++r) acc[mi][ni][r] = 0.f;

#pragma unroll 4
    for (int kg = 0; kg < 16; ++kg) {
        int go = kg * 8 + quad * 2;     // packed uint32 offset within row
        uint32_t ah[2][4], al[2][4];
#pragma unroll
        for (int mi = 0; mi < 2; ++mi) {
            uint2 h0 = *(const uint2*)(g_Ahi + (size_t)arow[mi][0] * 128 + go);
            uint2 h1 = *(const uint2*)(g_Ahi + (size_t)arow[mi][1] * 128 + go);
            ah[mi][0] = h0.x; ah[mi][1] = h1.x; ah[mi][2] = h0.y; ah[mi][3] = h1.y;
            uint2 q0 = *(const uint2*)(g_Alo + (size_t)arow[mi][0] * 128 + go);
            uint2 q1 = *(const uint2*)(g_Alo + (size_t)arow[mi][1] * 128 + go);
            al[mi][0] = q0.x; al[mi][1] = q1.x; al[mi][2] = q0.y; al[mi][3] = q1.y;
        }
        uint32_t bh[8][2], blo[8][2];
#pragma unroll
        for (int ni = 0; ni < 8; ++ni) {
            uint2 b0 = *(const uint2*)(Bh + (size_t)brow[ni] * 128 + go);
            bh[ni][0] = b0.x; bh[ni][1] = b0.y;
            uint2 b1 = *(const uint2*)(Bl + (size_t)brow[ni] * 128 + go);
            blo[ni][0] = b1.x; blo[ni][1] = b1.y;
        }
#pragma unroll
        for (int mi = 0; mi < 2; ++mi)
#pragma unroll
            for (int ni = 0; ni < 8; ++ni) {
                mma16816(acc[mi][ni], ah[mi], bh[ni]);
                mma16816(acc[mi][ni], ah[mi], blo[ni]);
                mma16816(acc[mi][ni], al[mi], bh[ni]);
            }
    }

    // epilogue: fp32 h + optional frag-packed bf16 split of h into cols 128:256
    float* outp = hbuf(out_sel);
#pragma unroll
    for (int mi = 0; mi < 2; ++mi) {
        int r0 = block_m + wm * 32 + mi * 16 + grp;
#pragma unroll
        for (int ni = 0; ni < 8; ++ni) {
            int col = wn * 64 + ni * 8 + quad * 2;
            float b0 = bl[col], b1 = bl[col + 1];
            int pidx = pk_idx(64 + (col >> 1));
            if (r0 < NN) {
                float2 v;
                v.x = fmaxf(acc[mi][ni][0] + b0, 0.f);
                v.y = fmaxf(acc[mi][ni][1] + b1, 0.f);
                *(float2*)(outp + (size_t)r0 * DD + col) = v;
                if (write_split) {
                    uint32_t hi, lo;
                    split2(v.x, v.y, hi, lo);
                    g_Ahi[(size_t)r0 * 128 + pidx] = hi;
                    g_Alo[(size_t)r0 * 128 + pidx] = lo;
                }
            }
            if (r0 + 8 < NN) {
                float2 v;
                v.x = fmaxf(acc[mi][ni][2] + b0, 0.f);
                v.y = fmaxf(acc[mi][ni][3] + b1, 0.f);
                *(float2*)(outp + (size_t)(r0 + 8) * DD + col) = v;
                if (write_split) {
                    uint32_t hi, lo;
                    split2(v.x, v.y, hi, lo);
                    g_Ahi[(size_t)(r0 + 8) * 128 + pidx] = hi;
                    g_Alo[(size_t)(r0 + 8) * 128 + pidx] = lo;
                }
            }
        }
    }
}

// ---------------- pooling: 128 threads per block, 64 nodes, flush on graph change ----------------
#define POOL_NODES 64
__global__ void __launch_bounds__(128) k_pool2(const int* __restrict__ batch) {
    int n0 = blockIdx.x * POOL_NODES;
    int col = threadIdx.x;
    if (n0 >= NN) return;
    int nend = n0 + POOL_NODES; if (nend > NN) nend = NN;
    int cur = batch[n0];
    float m = 0.f;
    for (int n = n0; n < nend; ++n) {
        int b = batch[n];
        if (b != cur) {
            atomicMax((int*)g_pool + (size_t)cur * DD + col, __float_as_int(m));
            m = 0.f;
            cur = b;
        }
        m = fmaxf(m, g_h1[(size_t)n * DD + col]);
    }
    atomicMax((int*)g_pool + (size_t)cur * DD + col, __float_as_int(m));
}

// ---------------- per-graph MLP head ----------------
__global__ void __launch_bounds__(256) k_head(const float* __restrict__ x,
                                              const float* __restrict__ Wf1, const float* __restrict__ bf1,
                                              const float* __restrict__ Wf2, const float* __restrict__ bf2,
                                              const float* __restrict__ Wsm, const float* __restrict__ bsm,
                                              const float* __restrict__ Wnews, const float* __restrict__ bnews,
                                              const float* __restrict__ Wcat, const float* __restrict__ bcat,
                                              float* __restrict__ out) {
    int b = blockIdx.x;
    int t = threadIdx.x;
    __shared__ float p[128], xr[128], t1[256], t2[128], sres[4];
    if (t < 128) {
        p[t] = g_pool[(size_t)b * DD + t];
        xr[t] = x[(size_t)g_root[b] * DD + t];
    }
    __syncthreads();
    {
        float acc = bf1[t];
#pragma unroll 4
        for (int k = 0; k < 128; k++) acc += p[k] * Wf1[k * 256 + t];
        t1[t] = fmaxf(acc, 0.f);
    }
    __syncthreads();
    if (t < 128) {
        float acc = bf2[t];
#pragma unroll 4
        for (int k = 0; k < 256; k++) acc += t1[k] * Wf2[k * 128 + t];
        t2[t] = fmaxf(acc, 0.f);
    }
    __syncthreads();
    if (t < 2) {
        float acc = bsm[t];
        for (int k = 0; k < 128; k++) acc += t2[k] * Wsm[k * 2 + t];
        sres[t] = fmaxf(acc, 0.f);
        float a2 = bnews[t];
        for (int k = 0; k < 128; k++) a2 += xr[k] * Wnews[k * 2 + t];
        sres[2 + t] = fmaxf(a2, 0.f);
    }
    __syncthreads();
    if (t == 0) {
        float o = bcat[0];
        for (int k = 0; k < 4; k++) o += sres[k] * Wcat[k];
        out[b] = 1.f / (1.f + expf(-o));
    }
}

// ---------------- launch ----------------
extern "C" void kernel_launch(void* const* d_in, const int* in_sizes, int n_in,
                              void* d_out, int out_size) {
    const float* x     = (const float*)d_in[0];
    const int*   ei    = (const int*)d_in[1];
    const int*   src   = ei;
    const int*   dst   = ei + EE;
    const int*   batch = (const int*)d_in[2];
    const float* Wl1 = (const float*)d_in[3];
    const float* Wr1 = (const float*)d_in[4];
    const float* bl1 = (const float*)d_in[5];
    const float* Wl2 = (const float*)d_in[6];
    const float* Wr2 = (const float*)d_in[7];
    const float* bl2 = (const float*)d_in[8];
    const float* Wl3 = (const float*)d_in[9];
    const float* Wr3 = (const float*)d_in[10];
    const float* bl3 = (const float*)d_in[11];
    const float* Wf1 = (const float*)d_in[12];
    const float* bf1 = (const float*)d_in[13];
    const float* Wf2 = (const float*)d_in[14];
    const float* bf2 = (const float*)d_in[15];
    const float* Wsm = (const float*)d_in[16];
    const float* bsm = (const float*)d_in[17];
    const float* Wnews = (const float*)d_in[18];
    const float* bnews = (const float*)d_in[19];
    const float* Wcat = (const float*)d_in[20];
    const float* bcat = (const float*)d_in[21];
    float* out = (float*)d_out;

    const int TB = 256;
    int gE = (EE + TB - 1) / TB;
    int gWarpN = (NN * 32 + TB - 1) / TB;
    int gPrep = (3 * DD * KK / 2 + TB - 1) / TB;

    k_init<<<256, TB>>>();                       // 1
    k_count<<<gE, TB>>>(dst);                    // 2
    k_scan_fused<<<1, 1024>>>(batch);            // 3
    k_fill<<<gE, TB>>>(src, dst);                // 4  <- profiled launch
    k_prep_w<<<gPrep, TB>>>(Wl1, Wr1, Wl2, Wr2, Wl3, Wr3);   // 5

    // layer 1 (agg also splits x into A[:,128:256])
    k_agg_split<<<gWarpN, TB>>>(x, -1, 1);       // 6
    k_gemm_hmma<<<GEMM_BLOCKS, 256>>>(bl1, 0, 1, 1);  // 7
    // layer 2
    k_agg_split<<<gWarpN, TB>>>(nullptr, 1, 0);  // 8
    k_gemm_hmma<<<GEMM_BLOCKS, 256>>>(bl2, 1, 2, 1);  // 9
    // layer 3
    k_agg_split<<<gWarpN, TB>>>(nullptr, 2, 0);  // 10
    k_gemm_hmma<<<GEMM_BLOCKS, 256>>>(bl3, 2, 1, 0);  // 11

    k_pool2<<<(NN + POOL_NODES - 1) / POOL_NODES, 128>>>(batch);  // 12
    k_head<<<BB, TB>>>(x, Wf1, bf1, Wf2, bf2, Wsm, bsm, Wnews, bnews, Wcat, bcat, out);  // 13
}